// round 3
// baseline (speedup 1.0000x reference)
#include <cuda_runtime.h>
#include <cstddef>

// Problem constants (from reference setup_inputs):
//   B=8, L=4096, D=512, HEAD h=16, n = L/h = 256
// Math collapses (k is all-ones => softmax over l is exactly uniform = 1/n):
//   A[b,n,h,l] = 1/256                        (q is unused)
//   V[b, n*16+h, d] = (1/256) * sum_{l=0..15} v[b, l*256+n, d]   (independent of h)
// Output = V (16,777,216 f32) followed by A (8,388,608 f32).

namespace {
constexpr int B = 8;
constexpr int L = 4096;
constexpr int D = 512;
constexpr int H = 16;
constexpr int N = 256;              // L / H
constexpr int D4 = D / 4;           // 128 float4 per row
constexpr long long V_ELEMS = (long long)B * L * D;        // 16,777,216
constexpr long long A_ELEMS = (long long)B * N * H * N;    // 8,388,608
constexpr float INV_N = 1.0f / 256.0f;

constexpr int TPB = 256;
constexpr int GRID = (B * N * D4) / TPB;                   // 1024 — single uniform wave
constexpr long long A_F4 = A_ELEMS / 4;                    // 2,097,152 float4
constexpr int A_PER_THREAD = (int)(A_F4 / ((long long)GRID * TPB)); // 8
}

// One uniform wave: every block does its V tile (1 item/thread) AND its
// proportional A slice (8 float4/thread). Identical work per block => no
// ragged tail, no wave transition. Streaming cache hints throughout.
__global__ void __launch_bounds__(TPB) fused_kernel(
    const float4* __restrict__ v, float4* __restrict__ out, int has_a)
{
    // ---- V: one thread per (b, n, dq) ----
    int idx = blockIdx.x * TPB + threadIdx.x;   // 0 .. 262143
    int dq = idx & (D4 - 1);                    // 0..127
    int n  = (idx >> 7) & (N - 1);              // 0..255
    int b  = idx >> 15;                         // 0..7

    const float4* vb = v + (size_t)b * L * D4 + (size_t)n * D4 + dq;

    // Two accumulators to keep more loads in flight under the reg budget.
    float4 acc0 = make_float4(0.f, 0.f, 0.f, 0.f);
    float4 acc1 = make_float4(0.f, 0.f, 0.f, 0.f);
    #pragma unroll
    for (int l = 0; l < H; l += 2) {
        float4 t0 = __ldcs(vb + (size_t)l * N * D4);
        float4 t1 = __ldcs(vb + (size_t)(l + 1) * N * D4);
        acc0.x += t0.x; acc0.y += t0.y; acc0.z += t0.z; acc0.w += t0.w;
        acc1.x += t1.x; acc1.y += t1.y; acc1.z += t1.z; acc1.w += t1.w;
    }
    float4 acc;
    acc.x = (acc0.x + acc1.x) * INV_N;
    acc.y = (acc0.y + acc1.y) * INV_N;
    acc.z = (acc0.z + acc1.z) * INV_N;
    acc.w = (acc0.w + acc1.w) * INV_N;

    float4* ob = out + (size_t)b * L * D4 + (size_t)(n * H) * D4 + dq;
    #pragma unroll
    for (int h = 0; h < H; ++h) {
        __stcs(ob + (size_t)h * D4, acc);
    }

    // ---- A fill: 8 coalesced float4 streaming stores per thread ----
    if (has_a) {
        float4* a = out + (V_ELEMS / 4);
        const float4 c = make_float4(INV_N, INV_N, INV_N, INV_N);
        long long base = (long long)blockIdx.x * TPB * A_PER_THREAD + threadIdx.x;
        #pragma unroll
        for (int k = 0; k < A_PER_THREAD; ++k) {
            __stcs(a + base + (long long)k * TPB, c);
        }
    }
}

extern "C" void kernel_launch(void* const* d_in, const int* in_sizes, int n_in,
                              void* d_out, int out_size)
{
    // Inputs: d_in[0] = q (mathematically irrelevant), d_in[1] = v.
    const float4* v = (const float4*)d_in[1];
    float4* out = (float4*)d_out;

    int has_a = ((long long)out_size >= V_ELEMS + A_ELEMS) ? 1 : 0;
    fused_kernel<<<GRID, TPB>>>(v, out, has_a);
}

// round 4
// speedup vs baseline: 1.0888x; 1.0888x over previous
#include <cuda_runtime.h>
#include <cstddef>

// Problem constants (from reference setup_inputs):
//   B=8, L=4096, D=512, HEAD h=16, n = L/h = 256
// Math collapses (k is all-ones => softmax over l is exactly uniform = 1/n):
//   A[b,n,h,l] = 1/256                        (q is unused)
//   V[b, n*16+h, d] = (1/256) * sum_{l=0..15} v[b, l*256+n, d]   (independent of h)
// Output = V (16,777,216 f32) followed by A (8,388,608 f32).

namespace {
constexpr int B = 8;
constexpr int L = 4096;
constexpr int D = 512;
constexpr int H = 16;
constexpr int N = 256;              // L / H
constexpr int D4 = D / 4;           // 128 float4 per row
constexpr long long V_ELEMS = (long long)B * L * D;        // 16,777,216
constexpr long long A_ELEMS = (long long)B * N * H * N;    // 8,388,608
constexpr float INV_N = 1.0f / 256.0f;

constexpr int TPB = 128;                                   // fine-grained blocks
constexpr int V_ITEMS = B * N * D4;                        // 262,144
constexpr int V_BLOCKS = V_ITEMS / TPB;                    // 2048
constexpr long long A_F4 = A_ELEMS / 4;                    // 2,097,152 float4
constexpr int FILL_PER_THREAD = 8;                         // 8 x float4 = 128B / thread
constexpr int A_BLOCKS = (int)(A_F4 / ((long long)TPB * FILL_PER_THREAD)); // 2048
}

// Fused kernel, fine-grained blocks: blocks [0, V_BLOCKS) do the V
// reduce+broadcast (one (b,n,dq) item per thread), blocks
// [V_BLOCKS, V_BLOCKS+A_BLOCKS) fill A with 1/256.
__global__ void __launch_bounds__(TPB) fused_kernel(
    const float4* __restrict__ v, float4* __restrict__ out)
{
    int blk = blockIdx.x;
    if (blk < V_BLOCKS) {
        // ---- V: one thread per (b, n, dq) ----
        int idx = blk * TPB + threadIdx.x;    // 0 .. 262143
        int dq = idx & (D4 - 1);              // 0..127
        int n  = (idx >> 7) & (N - 1);        // 0..255
        int b  = idx >> 15;                   // 0..7

        const float4* vb = v + (size_t)b * L * D4 + (size_t)n * D4 + dq;

        float4 acc = make_float4(0.f, 0.f, 0.f, 0.f);
        #pragma unroll
        for (int l = 0; l < H; ++l) {
            float4 t = vb[(size_t)l * N * D4];
            acc.x += t.x; acc.y += t.y; acc.z += t.z; acc.w += t.w;
        }
        acc.x *= INV_N; acc.y *= INV_N; acc.z *= INV_N; acc.w *= INV_N;

        float4* ob = out + (size_t)b * L * D4 + (size_t)(n * H) * D4 + dq;
        #pragma unroll
        for (int h = 0; h < H; ++h) {
            ob[(size_t)h * D4] = acc;
        }
    } else {
        // ---- A fill: 8 coalesced float4 stores per thread ----
        float4* a = out + (V_ELEMS / 4);
        const float4 c = make_float4(INV_N, INV_N, INV_N, INV_N);
        long long base = (long long)(blk - V_BLOCKS) * TPB * FILL_PER_THREAD
                       + threadIdx.x;
        #pragma unroll
        for (int k = 0; k < FILL_PER_THREAD; ++k) {
            a[base + (long long)k * TPB] = c;
        }
    }
}

extern "C" void kernel_launch(void* const* d_in, const int* in_sizes, int n_in,
                              void* d_out, int out_size)
{
    // Inputs: d_in[0] = q (mathematically irrelevant), d_in[1] = v.
    const float4* v = (const float4*)d_in[1];
    float4* out = (float4*)d_out;

    bool has_a = ((long long)out_size >= V_ELEMS + A_ELEMS);
    int grid = V_BLOCKS + (has_a ? A_BLOCKS : 0);   // 4096
    fused_kernel<<<grid, TPB>>>(v, out);
}